// round 1
// baseline (speedup 1.0000x reference)
#include <cuda_runtime.h>
#include <cstdint>

#define PATCH 14
#define HID   1024
#define KTOT  4096

#define BM 128
#define BN 128
#define BK 8
#define PAD 4

// src-row index table: idx[m*4 + ki] = source row in image_features for
// merged row m, k-block ki (ki in 0..3, column block of 1024).
// Max merged rows for this problem: 59808/4 = 14952; pad generously.
__device__ int g_idx[16384 * 4];

__global__ void build_idx_kernel(const int* __restrict__ sizes, int n_images, int M) {
    int m = blockIdx.x * blockDim.x + threadIdx.x;
    if (m >= M) return;
    int toff = 0, moff = 0;
    for (int i = 0; i < n_images; i++) {
        int h = sizes[2 * i] / PATCH;
        int w = sizes[2 * i + 1] / PATCH;
        int w2 = w >> 1;
        int mrows = (h >> 1) * w2;
        if (m < moff + mrows) {
            int r = m - moff;
            int gr = r / w2;
            int gc = r - gr * w2;
            int base = toff + (2 * gr) * w + 2 * gc;
            // merged[gr,gc, i,j, d] = tok[2gr+i, 2gc+j, d]; ki = i*2+j
            g_idx[m * 4 + 0] = base;          // (i=0,j=0)
            g_idx[m * 4 + 1] = base + 1;      // (i=0,j=1)
            g_idx[m * 4 + 2] = base + w;      // (i=1,j=0)
            g_idx[m * 4 + 3] = base + w + 1;  // (i=1,j=1)
            return;
        }
        toff += h * w;
        moff += mrows;
    }
}

// Classic 128x128x8 SGEMM with fused row-gather on A.
// A[m][k] = feat[g_idx[m*4 + (k>>10)]][k & 1023]
// B[k][n] = W[k*1024 + n]  (row-major, contiguous loads)
__global__ __launch_bounds__(256, 2) void merge_gemm_kernel(
    const float* __restrict__ feat, const float* __restrict__ Wm,
    float* __restrict__ out, int M)
{
    __shared__ float As[BK][BM + PAD];  // transposed A tile, padded (conflict-free)
    __shared__ float Bs[BK][BN];

    const int tid = threadIdx.x;
    const int bn = blockIdx.x * BN;
    const int bm = blockIdx.y * BM;
    const int tx = tid & 15;   // n-direction (8 cols each)
    const int ty = tid >> 4;   // m-direction (8 rows each)

    // A tile load mapping: 128 rows x 8 k -> one float4 (4 k's) per thread
    const int rowA = tid >> 1;
    const int kgA  = (tid & 1) << 2;
    // B tile load mapping: 8 k-rows x 128 n -> one float4 per thread
    const int rowB = tid >> 5;
    const int colB = (tid & 31) << 2;

    const int  m_a     = bm + rowA;
    const bool a_valid = (m_a < M);
    const int  mc      = a_valid ? m_a : (M - 1);
    const int idx0 = g_idx[mc * 4 + 0];
    const int idx1 = g_idx[mc * 4 + 1];
    const int idx2 = g_idx[mc * 4 + 2];
    const int idx3 = g_idx[mc * 4 + 3];

    float acc[8][8];
    #pragma unroll
    for (int i = 0; i < 8; i++)
        #pragma unroll
        for (int j = 0; j < 8; j++) acc[i][j] = 0.0f;

    for (int k0 = 0; k0 < KTOT; k0 += BK) {
        const int ki  = k0 >> 10;
        const int src = (ki == 0) ? idx0 : (ki == 1) ? idx1 : (ki == 2) ? idx2 : idx3;
        const int kc  = (k0 & 1023) + kgA;

        float4 av = make_float4(0.f, 0.f, 0.f, 0.f);
        if (a_valid)
            av = *(const float4*)(feat + (size_t)src * HID + kc);
        const float4 bv = *(const float4*)(Wm + (size_t)(k0 + rowB) * HID + bn + colB);

        As[kgA + 0][rowA] = av.x;
        As[kgA + 1][rowA] = av.y;
        As[kgA + 2][rowA] = av.z;
        As[kgA + 3][rowA] = av.w;
        *(float4*)&Bs[rowB][colB] = bv;
        __syncthreads();

        #pragma unroll
        for (int k = 0; k < BK; k++) {
            const float4 a0 = *(const float4*)&As[k][ty * 8];
            const float4 a1 = *(const float4*)&As[k][ty * 8 + 4];
            const float4 b0 = *(const float4*)&Bs[k][tx * 8];
            const float4 b1 = *(const float4*)&Bs[k][tx * 8 + 4];
            const float a[8] = {a0.x, a0.y, a0.z, a0.w, a1.x, a1.y, a1.z, a1.w};
            const float b[8] = {b0.x, b0.y, b0.z, b0.w, b1.x, b1.y, b1.z, b1.w};
            #pragma unroll
            for (int i = 0; i < 8; i++)
                #pragma unroll
                for (int j = 0; j < 8; j++)
                    acc[i][j] = fmaf(a[i], b[j], acc[i][j]);
        }
        __syncthreads();
    }

    #pragma unroll
    for (int i = 0; i < 8; i++) {
        const int r = bm + ty * 8 + i;
        if (r < M) {
            float4* o = (float4*)(out + (size_t)r * HID + bn + tx * 8);
            o[0] = make_float4(acc[i][0], acc[i][1], acc[i][2], acc[i][3]);
            o[1] = make_float4(acc[i][4], acc[i][5], acc[i][6], acc[i][7]);
        }
    }
}

extern "C" void kernel_launch(void* const* d_in, const int* in_sizes, int n_in,
                              void* d_out, int out_size) {
    const float* feat  = (const float*)d_in[0];   // [total_tokens, 1024] f32
    const int*   sizes = (const int*)  d_in[1];   // [n_images, 2] int32 (pixel sizes)
    const float* Wm    = (const float*)d_in[2];   // [4096, 1024] f32

    float* out = (float*)d_out;

    const int n_images = in_sizes[1] / 2;
    const int M        = out_size / HID;          // merged token count (14952)

    build_idx_kernel<<<(M + 255) / 256, 256>>>(sizes, n_images, M);

    dim3 grid(HID / BN, (M + BM - 1) / BM);       // N fastest: A tiles reused in L2
    merge_gemm_kernel<<<grid, 256>>>(feat, Wm, out, M);
}

// round 3
// speedup vs baseline: 2.7826x; 2.7826x over previous
#include <cuda_runtime.h>
#include <cuda_bf16.h>
#include <cstdint>

// out[M,1024] = merged[M,4096] @ W[4096,1024], fp32 via 3-pass bf16 HMMA.
// merged row m = concat of 4 gathered rows of image_features (2x2 patch merge).

#define PATCH 14
#define HID   1024
#define KTOT  4096
#define MPAD  15104

#define BM 128
#define BN 128
#define BK 32
#define NCHUNK (KTOT / BK)      // 128
#define LDS_STRIDE 40           // bf16 elems per smem row (80B: conflict-free)

// smem per stage: 4 tiles (Ah, Al, Bh, Bl), each 128 x 40 bf16 = 10240 B
#define TILE_BYTES 10240
#define STAGE_BYTES (4 * TILE_BYTES)    // 40960
#define SMEM_TOTAL (2 * STAGE_BYTES)    // 81920

// scratch (static device memory — no runtime allocation)
__device__ __align__(128) __nv_bfloat16 g_A_hi[(size_t)MPAD * KTOT];
__device__ __align__(128) __nv_bfloat16 g_A_lo[(size_t)MPAD * KTOT];
__device__ __align__(128) __nv_bfloat16 g_WT_hi[(size_t)HID * KTOT];
__device__ __align__(128) __nv_bfloat16 g_WT_lo[(size_t)HID * KTOT];

// ─── prep: gather + split fp32 -> bf16 hi/lo into merged [M,4096] layout ────
__global__ void convert_A_kernel(const float* __restrict__ feat,
                                 const int* __restrict__ sizes, int n_images) {
    const int bx = blockIdx.x;
    const int m  = bx >> 2;
    const int ki = bx & 3;
    int toff = 0, moff = 0, src = 0;
    for (int i = 0; i < n_images; i++) {
        const int h = sizes[2 * i] / PATCH, w = sizes[2 * i + 1] / PATCH;
        const int w2 = w >> 1, mr = (h >> 1) * w2;
        if (m < moff + mr) {
            const int r = m - moff;
            const int gr = r / w2, gc = r - gr * w2;
            src = toff + (2 * gr + (ki >> 1)) * w + 2 * gc + (ki & 1);
            break;
        }
        toff += h * w; moff += mr;
    }
    const int c = threadIdx.x * 4;
    const float4 x = *(const float4*)(feat + (size_t)src * HID + c);
    __nv_bfloat16 h0 = __float2bfloat16(x.x), h1 = __float2bfloat16(x.y);
    __nv_bfloat16 h2 = __float2bfloat16(x.z), h3 = __float2bfloat16(x.w);
    __nv_bfloat16 l0 = __float2bfloat16(x.x - __bfloat162float(h0));
    __nv_bfloat16 l1 = __float2bfloat16(x.y - __bfloat162float(h1));
    __nv_bfloat16 l2 = __float2bfloat16(x.z - __bfloat162float(h2));
    __nv_bfloat16 l3 = __float2bfloat16(x.w - __bfloat162float(h3));
    const size_t o = (size_t)m * KTOT + ki * HID + c;
    __nv_bfloat162* ph = (__nv_bfloat162*)(g_A_hi + o);
    __nv_bfloat162* pl = (__nv_bfloat162*)(g_A_lo + o);
    ph[0] = __nv_bfloat162(h0, h1); ph[1] = __nv_bfloat162(h2, h3);
    pl[0] = __nv_bfloat162(l0, l1); pl[1] = __nv_bfloat162(l2, l3);
}

// ─── prep: transpose W[4096,1024] -> WT[1024,4096] K-major, split hi/lo ─────
__global__ void convert_W_kernel(const float* __restrict__ Wm) {
    __shared__ float tile[32][33];
    const int k0 = blockIdx.x * 32, n0 = blockIdx.y * 32;
    const int tx = threadIdx.x, ty = threadIdx.y;
    #pragma unroll
    for (int i = 0; i < 4; i++)
        tile[ty + i * 8][tx] = Wm[(size_t)(k0 + ty + i * 8) * HID + n0 + tx];
    __syncthreads();
    #pragma unroll
    for (int i = 0; i < 4; i++) {
        const float x = tile[tx][ty + i * 8];
        const __nv_bfloat16 h = __float2bfloat16(x);
        const __nv_bfloat16 l = __float2bfloat16(x - __bfloat162float(h));
        const size_t o = (size_t)(n0 + ty + i * 8) * KTOT + k0 + tx;
        g_WT_hi[o] = h;
        g_WT_lo[o] = l;
    }
}

// ─── PTX helpers ────────────────────────────────────────────────────────────
__device__ __forceinline__ uint32_t smem_u32(const void* p) {
    uint32_t a;
    asm("{ .reg .u64 t; cvta.to.shared.u64 t, %1; cvt.u32.u64 %0, t; }" : "=r"(a) : "l"(p));
    return a;
}
__device__ __forceinline__ void cp16(uint32_t dst, const void* src) {
    asm volatile("cp.async.cg.shared.global [%0], [%1], 16;" :: "r"(dst), "l"(src));
}
__device__ __forceinline__ void ldsm_x4(uint32_t* r, uint32_t addr) {
    asm volatile("ldmatrix.sync.aligned.m8n8.x4.shared.b16 {%0,%1,%2,%3}, [%4];"
        : "=r"(r[0]), "=r"(r[1]), "=r"(r[2]), "=r"(r[3]) : "r"(addr));
}
__device__ __forceinline__ void mma_bf16(float* c, const uint32_t* a, const uint32_t* b) {
    asm volatile("mma.sync.aligned.m16n8k16.row.col.f32.bf16.bf16.f32 "
        "{%0,%1,%2,%3}, {%4,%5,%6,%7}, {%8,%9}, {%0,%1,%2,%3};"
        : "+f"(c[0]), "+f"(c[1]), "+f"(c[2]), "+f"(c[3])
        : "r"(a[0]), "r"(a[1]), "r"(a[2]), "r"(a[3]), "r"(b[0]), "r"(b[1]));
}

// ─── main GEMM ──────────────────────────────────────────────────────────────
__global__ __launch_bounds__(256, 2) void gemm3x_kernel(float* __restrict__ out, int M) {
    extern __shared__ __align__(128) char smem[];
    const uint32_t sb = smem_u32(smem);
    const int tid  = threadIdx.x;
    const int lane = tid & 31;
    const int wid  = tid >> 5;
    const int wm   = wid & 1;          // 2 warps in M (64 rows each)
    const int wn   = wid >> 1;         // 4 warps in N (32 cols each)

    const int m0 = blockIdx.y * BM;
    const int n0 = blockIdx.x * BN;

    // cp.async mapping: 2 segments of 16B per thread per tile
    const int seg0 = tid * 2;
    const int r0c  = seg0 >> 2;                 // row 0..127
    const int ks0  = (seg0 & 3) * 8;            // k elem offset 0/8/16/24
    const int r1c  = (seg0 + 1) >> 2;
    const int ks1  = ((seg0 + 1) & 3) * 8;

    // clamped global rows for A (tail tile), exact rows for B
    const int gra0 = min(m0 + r0c, M - 1);
    const int gra1 = min(m0 + r1c, M - 1);
    const int grb0 = n0 + r0c;
    const int grb1 = n0 + r1c;

    // smem dst offsets (bytes), stage-relative
    const uint32_t dA0 = r0c * (LDS_STRIDE * 2) + ks0 * 2;
    const uint32_t dA1 = r1c * (LDS_STRIDE * 2) + ks1 * 2;

    float acc[4][4][4];
    #pragma unroll
    for (int i = 0; i < 4; i++)
        #pragma unroll
        for (int j = 0; j < 4; j++)
            #pragma unroll
            for (int q = 0; q < 4; q++) acc[i][j][q] = 0.0f;

    // fragment smem addresses (byte), stage-relative
    // A: tile i (m16), k-half kk: row = wm*64 + i*16 + (lane&15), col = kk*16 + (lane>>4)*8
    const uint32_t aoff = (uint32_t)((wm * 64 + (lane & 15)) * LDS_STRIDE + (lane >> 4) * 8) * 2;
    // B: pair jj (n16), k-half kk: n = wn*32 + jj*16 + ((lane>>4)&1)*8 + (lane&7),
    //                              k = kk*16 + ((lane>>3)&1)*8
    const uint32_t boff = (uint32_t)((wn * 32 + ((lane >> 4) & 1) * 8 + (lane & 7)) * LDS_STRIDE
                                     + ((lane >> 3) & 1) * 8) * 2;

    auto load_chunk = [&](int c, int buf) {
        const int k0 = c * BK;
        const uint32_t base = sb + buf * STAGE_BYTES;
        const uint32_t sAh = base, sAl = base + TILE_BYTES;
        const uint32_t sBh = base + 2 * TILE_BYTES, sBl = base + 3 * TILE_BYTES;
        cp16(sAh + dA0, g_A_hi + (size_t)gra0 * KTOT + k0 + ks0);
        cp16(sAh + dA1, g_A_hi + (size_t)gra1 * KTOT + k0 + ks1);
        cp16(sAl + dA0, g_A_lo + (size_t)gra0 * KTOT + k0 + ks0);
        cp16(sAl + dA1, g_A_lo + (size_t)gra1 * KTOT + k0 + ks1);
        cp16(sBh + dA0, g_WT_hi + (size_t)grb0 * KTOT + k0 + ks0);
        cp16(sBh + dA1, g_WT_hi + (size_t)grb1 * KTOT + k0 + ks1);
        cp16(sBl + dA0, g_WT_lo + (size_t)grb0 * KTOT + k0 + ks0);
        cp16(sBl + dA1, g_WT_lo + (size_t)grb1 * KTOT + k0 + ks1);
    };

    auto compute_chunk = [&](int buf) {
        const uint32_t base = sb + buf * STAGE_BYTES;
        const uint32_t sAh = base, sAl = base + TILE_BYTES;
        const uint32_t sBh = base + 2 * TILE_BYTES, sBl = base + 3 * TILE_BYTES;
        #pragma unroll
        for (int kk = 0; kk < 2; kk++) {
            const uint32_t kb = kk * 32;   // 16 bf16 = 32 bytes
            uint32_t a[4][4], bh[2][4], bx[2][4];
            #pragma unroll
            for (int i = 0; i < 4; i++)
                ldsm_x4(a[i], sAh + aoff + i * (16 * LDS_STRIDE * 2) + kb);
            #pragma unroll
            for (int jj = 0; jj < 2; jj++)
                ldsm_x4(bh[jj], sBh + boff + jj * (16 * LDS_STRIDE * 2) + kb);
            // pass 1: Ah * Bh
            #pragma unroll
            for (int i = 0; i < 4; i++)
                #pragma unroll
                for (int j = 0; j < 4; j++)
                    mma_bf16(acc[i][j], a[i], &bh[j >> 1][(j & 1) * 2]);
            // pass 2: Ah * Bl
            #pragma unroll
            for (int jj = 0; jj < 2; jj++)
                ldsm_x4(bx[jj], sBl + boff + jj * (16 * LDS_STRIDE * 2) + kb);
            #pragma unroll
            for (int i = 0; i < 4; i++)
                #pragma unroll
                for (int j = 0; j < 4; j++)
                    mma_bf16(acc[i][j], a[i], &bx[j >> 1][(j & 1) * 2]);
            // pass 3: Al * Bh
            #pragma unroll
            for (int i = 0; i < 4; i++)
                ldsm_x4(a[i], sAl + aoff + i * (16 * LDS_STRIDE * 2) + kb);
            #pragma unroll
            for (int i = 0; i < 4; i++)
                #pragma unroll
                for (int j = 0; j < 4; j++)
                    mma_bf16(acc[i][j], a[i], &bh[j >> 1][(j & 1) * 2]);
        }
    };

    load_chunk(0, 0);
    asm volatile("cp.async.commit_group;" ::: "memory");

    #pragma unroll 1
    for (int c = 0; c < NCHUNK; c++) {
        if (c + 1 < NCHUNK) {
            load_chunk(c + 1, (c + 1) & 1);
            asm volatile("cp.async.commit_group;" ::: "memory");
            asm volatile("cp.async.wait_group 1;" ::: "memory");
        } else {
            asm volatile("cp.async.wait_group 0;" ::: "memory");
        }
        __syncthreads();
        compute_chunk(c & 1);
        __syncthreads();
    }

    // epilogue
    const int g = lane >> 2, t = lane & 3;
    #pragma unroll
    for (int i = 0; i < 4; i++) {
        #pragma unroll
        for (int j = 0; j < 4; j++) {
            const int r = m0 + wm * 64 + i * 16 + g;
            const int cc = n0 + wn * 32 + j * 8 + t * 2;
            if (r < M)
                *(float2*)(out + (size_t)r * HID + cc) =
                    make_float2(acc[i][j][0], acc[i][j][1]);
            if (r + 8 < M)
                *(float2*)(out + (size_t)(r + 8) * HID + cc) =
                    make_float2(acc[i][j][2], acc[i][j][3]);
        }
    }
}

// ─── host ───────────────────────────────────────────────────────────────────
extern "C" void kernel_launch(void* const* d_in, const int* in_sizes, int n_in,
                              void* d_out, int out_size) {
    const float* feat  = (const float*)d_in[0];
    const int*   sizes = (const int*)  d_in[1];
    const float* Wm    = (const float*)d_in[2];
    float* out = (float*)d_out;

    const int n_images = in_sizes[1] / 2;
    const int M        = out_size / HID;

    convert_A_kernel<<<M * 4, 256>>>(feat, sizes, n_images);
    convert_W_kernel<<<dim3(KTOT / 32, HID / 32), dim3(32, 8)>>>(Wm);

    static bool attr_set = false;
    if (!attr_set) {
        cudaFuncSetAttribute(gemm3x_kernel,
                             cudaFuncAttributeMaxDynamicSharedMemorySize, SMEM_TOTAL);
        attr_set = true;
    }
    dim3 grid(HID / BN, (M + BM - 1) / BM);   // (8, 117), N fastest for L2 reuse
    gemm3x_kernel<<<grid, 256, SMEM_TOTAL>>>(out, M);
}

// round 4
// speedup vs baseline: 3.7672x; 1.3538x over previous
#include <cuda_runtime.h>
#include <cuda_fp16.h>
#include <cstdint>

// out[M,1024] = merged[M,4096] @ W[4096,1024], fp32 via 2-pass fp16 HMMA:
//   out ≈ fp16(A)·Bh + fp16(A)·Bl, where W = Bh + Bl (fp16 2-term split).
// merged row m = concat of 4 gathered rows of image_features (2x2 patch merge).

#define PATCH 14
#define HID   1024
#define KTOT  4096
#define MPAD  15104

#define BM 128
#define BN 128
#define BK 32
#define NCHUNK (KTOT / BK)        // 128
#define LDSTR  40                  // half elems per smem row (80 B, ldsm conflict-free)
#define TILE_B (128 * LDSTR * 2)   // 10240
#define STAGE_B (3 * TILE_B)       // 30720 : Ah | Bh | Bl
#define NSTAGE 3
#define SMEM_TOTAL (NSTAGE * STAGE_B)   // 92160 -> 2 CTAs/SM

// scratch (static device memory — no runtime allocation)
__device__ int g_idx[16384 * 4];
__device__ __align__(128) __half g_Ah[(size_t)MPAD * KTOT];
__device__ __align__(128) __half g_Bh[(size_t)HID * KTOT];
__device__ __align__(128) __half g_Bl[(size_t)HID * KTOT];

// ─── prep: merged-row -> source-row index table ─────────────────────────────
__global__ void build_idx_kernel(const int* __restrict__ sizes, int n_images, int M) {
    int m = blockIdx.x * blockDim.x + threadIdx.x;
    if (m >= M) return;
    int toff = 0, moff = 0;
    for (int i = 0; i < n_images; i++) {
        int h = sizes[2 * i] / PATCH;
        int w = sizes[2 * i + 1] / PATCH;
        int w2 = w >> 1;
        int mrows = (h >> 1) * w2;
        if (m < moff + mrows) {
            int r = m - moff;
            int gr = r / w2;
            int gc = r - gr * w2;
            int base = toff + (2 * gr) * w + 2 * gc;
            g_idx[m * 4 + 0] = base;
            g_idx[m * 4 + 1] = base + 1;
            g_idx[m * 4 + 2] = base + w;
            g_idx[m * 4 + 3] = base + w + 1;
            return;
        }
        toff += h * w;
        moff += mrows;
    }
}

// ─── prep: gather + fp32 -> fp16 into merged [M,4096] layout ────────────────
__global__ void convert_A_kernel(const float* __restrict__ feat) {
    const int m  = blockIdx.x >> 2;
    const int ki = blockIdx.x & 3;
    const int src = g_idx[m * 4 + ki];
    const int c = threadIdx.x * 4;
    const float4 x = *(const float4*)(feat + (size_t)src * HID + c);
    __half2* p = (__half2*)(g_Ah + (size_t)m * KTOT + ki * HID + c);
    p[0] = __floats2half2_rn(x.x, x.y);
    p[1] = __floats2half2_rn(x.z, x.w);
}

// ─── prep: transpose W[4096,1024] -> [1024,4096] K-major, fp16 hi/lo ────────
__global__ void convert_W_kernel(const float* __restrict__ Wm) {
    __shared__ float tile[32][33];
    const int k0 = blockIdx.x * 32, n0 = blockIdx.y * 32;
    const int tx = threadIdx.x, ty = threadIdx.y;
    #pragma unroll
    for (int i = 0; i < 4; i++)
        tile[ty + i * 8][tx] = Wm[(size_t)(k0 + ty + i * 8) * HID + n0 + tx];
    __syncthreads();
    #pragma unroll
    for (int i = 0; i < 4; i++) {
        const float x = tile[tx][ty + i * 8];
        const __half h = __float2half_rn(x);
        const __half l = __float2half_rn(x - __half2float(h));
        const size_t o = (size_t)(n0 + ty + i * 8) * KTOT + k0 + tx;
        g_Bh[o] = h;
        g_Bl[o] = l;
    }
}

// ─── PTX helpers ────────────────────────────────────────────────────────────
__device__ __forceinline__ uint32_t smem_u32(const void* p) {
    uint32_t a;
    asm("{ .reg .u64 t; cvta.to.shared.u64 t, %1; cvt.u32.u64 %0, t; }" : "=r"(a) : "l"(p));
    return a;
}
__device__ __forceinline__ void cp16(uint32_t dst, const void* src) {
    asm volatile("cp.async.cg.shared.global [%0], [%1], 16;" :: "r"(dst), "l"(src));
}
__device__ __forceinline__ void ldsm_x4(uint32_t* r, uint32_t addr) {
    asm volatile("ldmatrix.sync.aligned.m8n8.x4.shared.b16 {%0,%1,%2,%3}, [%4];"
        : "=r"(r[0]), "=r"(r[1]), "=r"(r[2]), "=r"(r[3]) : "r"(addr));
}
__device__ __forceinline__ void mma_f16(float* c, const uint32_t* a, const uint32_t* b) {
    asm volatile("mma.sync.aligned.m16n8k16.row.col.f32.f16.f16.f32 "
        "{%0,%1,%2,%3}, {%4,%5,%6,%7}, {%8,%9}, {%0,%1,%2,%3};"
        : "+f"(c[0]), "+f"(c[1]), "+f"(c[2]), "+f"(c[3])
        : "r"(a[0]), "r"(a[1]), "r"(a[2]), "r"(a[3]), "r"(b[0]), "r"(b[1]));
}

// ─── main GEMM: 128x128 CTA, 8 warps (64x32 warp tile), 3-stage cp.async ────
__global__ __launch_bounds__(256, 2) void gemm2x_kernel(float* __restrict__ out, int M) {
    extern __shared__ __align__(128) char smem[];
    const uint32_t sb = smem_u32(smem);
    const int tid  = threadIdx.x;
    const int lane = tid & 31;
    const int wid  = tid >> 5;
    const int wm   = wid & 1;
    const int wn   = wid >> 1;

    const int m0 = blockIdx.y * BM;
    const int n0 = blockIdx.x * BN;

    // cp.async mapping: 2 x 16B segments per thread per tile (128 rows x 32 half)
    const int q0 = tid * 2, q1 = tid * 2 + 1;
    const int r0 = q0 >> 2, ks0 = (q0 & 3) * 8;
    const int r1 = q1 >> 2, ks1 = (q1 & 3) * 8;
    const int gra0 = min(m0 + r0, M - 1);
    const int gra1 = min(m0 + r1, M - 1);
    const int grb0 = n0 + r0, grb1 = n0 + r1;
    const uint32_t d0 = r0 * (LDSTR * 2) + ks0 * 2;
    const uint32_t d1 = r1 * (LDSTR * 2) + ks1 * 2;

    float acc[4][4][4];
    #pragma unroll
    for (int i = 0; i < 4; i++)
        #pragma unroll
        for (int j = 0; j < 4; j++)
            #pragma unroll
            for (int q = 0; q < 4; q++) acc[i][j][q] = 0.0f;

    // ldmatrix fragment addresses (byte, stage-relative), verified in R3
    const uint32_t aoff = (uint32_t)((wm * 64 + (lane & 15)) * LDSTR + (lane >> 4) * 8) * 2;
    const uint32_t boff = (uint32_t)((wn * 32 + ((lane >> 4) & 1) * 8 + (lane & 7)) * LDSTR
                                     + ((lane >> 3) & 1) * 8) * 2;

    auto cp_chunk = [&](int c, int st) {
        const uint32_t base = sb + st * STAGE_B;
        const int k0 = c * BK;
        cp16(base + d0,              g_Ah + (size_t)gra0 * KTOT + k0 + ks0);
        cp16(base + d1,              g_Ah + (size_t)gra1 * KTOT + k0 + ks1);
        cp16(base + TILE_B + d0,     g_Bh + (size_t)grb0 * KTOT + k0 + ks0);
        cp16(base + TILE_B + d1,     g_Bh + (size_t)grb1 * KTOT + k0 + ks1);
        cp16(base + 2 * TILE_B + d0, g_Bl + (size_t)grb0 * KTOT + k0 + ks0);
        cp16(base + 2 * TILE_B + d1, g_Bl + (size_t)grb1 * KTOT + k0 + ks1);
    };

    auto compute_chunk = [&](int st) {
        const uint32_t base = sb + st * STAGE_B;
        #pragma unroll
        for (int kk = 0; kk < 2; kk++) {
            const uint32_t kb = kk * 32;
            uint32_t a[4][4], bh[2][4], bl[2][4];
            #pragma unroll
            for (int i = 0; i < 4; i++)
                ldsm_x4(a[i], base + aoff + i * (16 * LDSTR * 2) + kb);
            #pragma unroll
            for (int jj = 0; jj < 2; jj++)
                ldsm_x4(bh[jj], base + TILE_B + boff + jj * (16 * LDSTR * 2) + kb);
            #pragma unroll
            for (int jj = 0; jj < 2; jj++)
                ldsm_x4(bl[jj], base + 2 * TILE_B + boff + jj * (16 * LDSTR * 2) + kb);
            #pragma unroll
            for (int i = 0; i < 4; i++)
                #pragma unroll
                for (int j = 0; j < 4; j++)
                    mma_f16(acc[i][j], a[i], &bh[j >> 1][(j & 1) * 2]);
            #pragma unroll
            for (int i = 0; i < 4; i++)
                #pragma unroll
                for (int j = 0; j < 4; j++)
                    mma_f16(acc[i][j], a[i], &bl[j >> 1][(j & 1) * 2]);
        }
    };

    // 3-stage pipeline
    cp_chunk(0, 0);
    asm volatile("cp.async.commit_group;" ::: "memory");
    cp_chunk(1, 1);
    asm volatile("cp.async.commit_group;" ::: "memory");

    int st_c = 0;   // compute stage
    int st_p = 2;   // prefetch stage
    #pragma unroll 1
    for (int c = 0; c < NCHUNK; c++) {
        if (c + 2 < NCHUNK) cp_chunk(c + 2, st_p);
        asm volatile("cp.async.commit_group;" ::: "memory");   // (possibly empty)
        asm volatile("cp.async.wait_group 2;" ::: "memory");   // chunk c's group done
        __syncthreads();                                        // all warps' cp(c) visible
        compute_chunk(st_c);
        __syncthreads();                                        // stage free for reuse
        if (++st_c == NSTAGE) st_c = 0;
        if (++st_p == NSTAGE) st_p = 0;
    }

    // epilogue
    const int g = lane >> 2, t = lane & 3;
    #pragma unroll
    for (int i = 0; i < 4; i++) {
        #pragma unroll
        for (int j = 0; j < 4; j++) {
            const int r  = m0 + wm * 64 + i * 16 + g;
            const int cc = n0 + wn * 32 + j * 8 + t * 2;
            if (r < M)
                *(float2*)(out + (size_t)r * HID + cc) =
                    make_float2(acc[i][j][0], acc[i][j][1]);
            if (r + 8 < M)
                *(float2*)(out + (size_t)(r + 8) * HID + cc) =
                    make_float2(acc[i][j][2], acc[i][j][3]);
        }
    }
}

// ─── host ───────────────────────────────────────────────────────────────────
extern "C" void kernel_launch(void* const* d_in, const int* in_sizes, int n_in,
                              void* d_out, int out_size) {
    const float* feat  = (const float*)d_in[0];
    const int*   sizes = (const int*)  d_in[1];
    const float* Wm    = (const float*)d_in[2];
    float* out = (float*)d_out;

    const int n_images = in_sizes[1] / 2;
    const int M        = out_size / HID;

    build_idx_kernel<<<(M + 255) / 256, 256>>>(sizes, n_images, M);
    convert_A_kernel<<<M * 4, 256>>>(feat);
    convert_W_kernel<<<dim3(KTOT / 32, HID / 32), dim3(32, 8)>>>(Wm);

    static bool attr_set = false;
    if (!attr_set) {
        cudaFuncSetAttribute(gemm2x_kernel,
                             cudaFuncAttributeMaxDynamicSharedMemorySize, SMEM_TOTAL);
        attr_set = true;
    }
    dim3 grid(HID / BN, (M + BM - 1) / BM);   // (8, 117): N fastest -> A shared in L2
    gemm2x_kernel<<<grid, 256, SMEM_TOTAL>>>(out, M);
}

// round 5
// speedup vs baseline: 5.4385x; 1.4436x over previous
#include <cuda_runtime.h>
#include <cuda_fp16.h>
#include <cstdint>

// out[M,1024] = merged[M,4096] @ W[4096,1024], fp32 via 2-pass fp16 HMMA:
//   out ≈ fp16(A)·Bh + fp16(A)·Bl, where W = Bh + Bl (fp16 2-term split).
// merged row m = concat of 4 gathered rows of image_features (2x2 patch merge).

#define PATCH 14
#define HID   1024
#define KTOT  4096
#define MPAD  15104

#define BM 128
#define BN 128
#define BK 64                      // 64 halves = 128 B row: natural SW128 atom
#define NCHUNK (KTOT / BK)         // 64
#define TILE_B (128 * 128)         // 16384 B (128 rows x 128 B), XOR-swizzled
#define STAGE_B (3 * TILE_B)       // 49152 : Ah | Bh | Bl
#define NSTAGE 2
#define SMEM_TOTAL (NSTAGE * STAGE_B)   // 98304 -> 2 CTAs/SM

// scratch (static device memory — no runtime allocation)
__device__ int g_idx[16384 * 4];
__device__ __align__(128) __half g_Ah[(size_t)MPAD * KTOT];
__device__ __align__(128) __half g_Bh[(size_t)HID * KTOT];
__device__ __align__(128) __half g_Bl[(size_t)HID * KTOT];

// ─── prep: merged-row -> source-row index table ─────────────────────────────
__global__ void build_idx_kernel(const int* __restrict__ sizes, int n_images, int M) {
    int m = blockIdx.x * blockDim.x + threadIdx.x;
    if (m >= M) return;
    int toff = 0, moff = 0;
    for (int i = 0; i < n_images; i++) {
        int h = sizes[2 * i] / PATCH;
        int w = sizes[2 * i + 1] / PATCH;
        int w2 = w >> 1;
        int mrows = (h >> 1) * w2;
        if (m < moff + mrows) {
            int r = m - moff;
            int gr = r / w2;
            int gc = r - gr * w2;
            int base = toff + (2 * gr) * w + 2 * gc;
            g_idx[m * 4 + 0] = base;
            g_idx[m * 4 + 1] = base + 1;
            g_idx[m * 4 + 2] = base + w;
            g_idx[m * 4 + 3] = base + w + 1;
            return;
        }
        toff += h * w;
        moff += mrows;
    }
}

// ─── prep: gather + fp32 -> fp16 into merged [M,4096] layout ────────────────
__global__ void convert_A_kernel(const float* __restrict__ feat) {
    const int m  = blockIdx.x >> 2;
    const int ki = blockIdx.x & 3;
    const int src = g_idx[m * 4 + ki];
    const int c = threadIdx.x * 4;
    const float4 x = *(const float4*)(feat + (size_t)src * HID + c);
    __half2* p = (__half2*)(g_Ah + (size_t)m * KTOT + ki * HID + c);
    p[0] = __floats2half2_rn(x.x, x.y);
    p[1] = __floats2half2_rn(x.z, x.w);
}

// ─── prep: transpose W[4096,1024] -> [1024,4096] K-major, fp16 hi/lo ────────
__global__ void convert_W_kernel(const float* __restrict__ Wm) {
    __shared__ float tile[32][33];
    const int k0 = blockIdx.x * 32, n0 = blockIdx.y * 32;
    const int tx = threadIdx.x, ty = threadIdx.y;
    #pragma unroll
    for (int i = 0; i < 4; i++)
        tile[ty + i * 8][tx] = Wm[(size_t)(k0 + ty + i * 8) * HID + n0 + tx];
    __syncthreads();
    #pragma unroll
    for (int i = 0; i < 4; i++) {
        const float x = tile[tx][ty + i * 8];
        const __half h = __float2half_rn(x);
        const __half l = __float2half_rn(x - __half2float(h));
        const size_t o = (size_t)(n0 + ty + i * 8) * KTOT + k0 + tx;
        g_Bh[o] = h;
        g_Bl[o] = l;
    }
}

// ─── PTX helpers ────────────────────────────────────────────────────────────
__device__ __forceinline__ uint32_t smem_u32(const void* p) {
    uint32_t a;
    asm("{ .reg .u64 t; cvta.to.shared.u64 t, %1; cvt.u32.u64 %0, t; }" : "=r"(a) : "l"(p));
    return a;
}
__device__ __forceinline__ void cp16(uint32_t dst, const void* src) {
    asm volatile("cp.async.cg.shared.global [%0], [%1], 16;" :: "r"(dst), "l"(src));
}
__device__ __forceinline__ void ldsm_x4(uint32_t* r, uint32_t addr) {
    asm volatile("ldmatrix.sync.aligned.m8n8.x4.shared.b16 {%0,%1,%2,%3}, [%4];"
        : "=r"(r[0]), "=r"(r[1]), "=r"(r[2]), "=r"(r[3]) : "r"(addr));
}
__device__ __forceinline__ void mma_f16(float* c, const uint32_t* a, const uint32_t* b) {
    asm volatile("mma.sync.aligned.m16n8k16.row.col.f32.f16.f16.f32 "
        "{%0,%1,%2,%3}, {%4,%5,%6,%7}, {%8,%9}, {%0,%1,%2,%3};"
        : "+f"(c[0]), "+f"(c[1]), "+f"(c[2]), "+f"(c[3])
        : "r"(a[0]), "r"(a[1]), "r"(a[2]), "r"(a[3]), "r"(b[0]), "r"(b[1]));
}

// ─── main GEMM: 128x128 CTA, 8 warps (64x32 warp tile), BK=64, swizzled ─────
__global__ __launch_bounds__(256, 2) void gemm2x_kernel(float* __restrict__ out, int M) {
    extern __shared__ __align__(128) char smem[];
    const uint32_t sb = smem_u32(smem);
    const int tid  = threadIdx.x;
    const int lane = tid & 31;
    const int wid  = tid >> 5;
    const int wm   = wid & 1;
    const int wn   = wid >> 1;

    const int m0 = blockIdx.y * BM;
    const int n0 = blockIdx.x * BN;

    // cp.async mapping: tile = 128 rows x 8 x 16B; thread t covers segs t+256j
    int cp_row[4], cp_col[4];
    uint32_t cp_dst[4];
    #pragma unroll
    for (int j = 0; j < 4; j++) {
        const int s = tid + 256 * j;
        cp_row[j] = s >> 3;
        cp_col[j] = s & 7;
        cp_dst[j] = cp_row[j] * 128 + ((cp_col[j] ^ (cp_row[j] & 7)) << 4);
    }
    int gra[4], grb[4];
    #pragma unroll
    for (int j = 0; j < 4; j++) {
        gra[j] = min(m0 + cp_row[j], M - 1);
        grb[j] = n0 + cp_row[j];
    }

    float acc[4][4][4];
    #pragma unroll
    for (int i = 0; i < 4; i++)
        #pragma unroll
        for (int j = 0; j < 4; j++)
            #pragma unroll
            for (int q = 0; q < 4; q++) acc[i][j][q] = 0.0f;

    // ldmatrix lane-constant pieces (swizzle bits constant: row offsets % 8 == 0)
    const int arow = wm * 64 + (lane & 15);
    const int asel = lane >> 4;                               // 16B-unit select
    const int aswz = arow & 7;
    const int brow = wn * 32 + ((lane >> 4) & 1) * 8 + (lane & 7);
    const int bsel = (lane >> 3) & 1;
    const int bswz = brow & 7;

    auto cp_chunk = [&](int c, int st) {
        const uint32_t base = sb + st * STAGE_B;
        const int k0 = c * BK;
        #pragma unroll
        for (int j = 0; j < 4; j++) {
            const int ko = k0 + cp_col[j] * 8;
            cp16(base + cp_dst[j],              g_Ah + (size_t)gra[j] * KTOT + ko);
            cp16(base + TILE_B + cp_dst[j],     g_Bh + (size_t)grb[j] * KTOT + ko);
            cp16(base + 2 * TILE_B + cp_dst[j], g_Bl + (size_t)grb[j] * KTOT + ko);
        }
    };

    auto compute_chunk = [&](int st) {
        const uint32_t base = sb + st * STAGE_B;
        #pragma unroll
        for (int kk = 0; kk < 4; kk++) {
            uint32_t a[4][4], bh[2][4], bl[2][4];
            const uint32_t acol = (uint32_t)(((kk * 2 + asel) ^ aswz) << 4);
            const uint32_t bcol = (uint32_t)(((kk * 2 + bsel) ^ bswz) << 4);
            #pragma unroll
            for (int i = 0; i < 4; i++)
                ldsm_x4(a[i], base + (arow + i * 16) * 128 + acol);
            #pragma unroll
            for (int jj = 0; jj < 2; jj++)
                ldsm_x4(bh[jj], base + TILE_B + (brow + jj * 16) * 128 + bcol);
            #pragma unroll
            for (int jj = 0; jj < 2; jj++)
                ldsm_x4(bl[jj], base + 2 * TILE_B + (brow + jj * 16) * 128 + bcol);
            #pragma unroll
            for (int i = 0; i < 4; i++)
                #pragma unroll
                for (int j = 0; j < 4; j++)
                    mma_f16(acc[i][j], a[i], &bh[j >> 1][(j & 1) * 2]);
            #pragma unroll
            for (int i = 0; i < 4; i++)
                #pragma unroll
                for (int j = 0; j < 4; j++)
                    mma_f16(acc[i][j], a[i], &bl[j >> 1][(j & 1) * 2]);
        }
    };

    // 2-stage pipeline, 64 iterations
    cp_chunk(0, 0);
    asm volatile("cp.async.commit_group;" ::: "memory");

    #pragma unroll 1
    for (int c = 0; c < NCHUNK; c++) {
        if (c + 1 < NCHUNK) {
            cp_chunk(c + 1, (c + 1) & 1);
            asm volatile("cp.async.commit_group;" ::: "memory");
            asm volatile("cp.async.wait_group 1;" ::: "memory");
        } else {
            asm volatile("cp.async.wait_group 0;" ::: "memory");
        }
        __syncthreads();               // chunk c visible to all warps
        compute_chunk(c & 1);
        __syncthreads();               // stage (c&1) free for next overwrite
    }

    // epilogue
    const int g = lane >> 2, t = lane & 3;
    #pragma unroll
    for (int i = 0; i < 4; i++) {
        #pragma unroll
        for (int j = 0; j < 4; j++) {
            const int r  = m0 + wm * 64 + i * 16 + g;
            const int cc = n0 + wn * 32 + j * 8 + t * 2;
            if (r < M)
                *(float2*)(out + (size_t)r * HID + cc) =
                    make_float2(acc[i][j][0], acc[i][j][1]);
            if (r + 8 < M)
                *(float2*)(out + (size_t)(r + 8) * HID + cc) =
                    make_float2(acc[i][j][2], acc[i][j][3]);
        }
    }
}

// ─── host ───────────────────────────────────────────────────────────────────
extern "C" void kernel_launch(void* const* d_in, const int* in_sizes, int n_in,
                              void* d_out, int out_size) {
    const float* feat  = (const float*)d_in[0];
    const int*   sizes = (const int*)  d_in[1];
    const float* Wm    = (const float*)d_in[2];
    float* out = (float*)d_out;

    const int n_images = in_sizes[1] / 2;
    const int M        = out_size / HID;

    build_idx_kernel<<<(M + 255) / 256, 256>>>(sizes, n_images, M);
    convert_A_kernel<<<M * 4, 256>>>(feat);
    convert_W_kernel<<<dim3(KTOT / 32, HID / 32), dim3(32, 8)>>>(Wm);

    static bool attr_set = false;
    if (!attr_set) {
        cudaFuncSetAttribute(gemm2x_kernel,
                             cudaFuncAttributeMaxDynamicSharedMemorySize, SMEM_TOTAL);
        attr_set = true;
    }
    dim3 grid(HID / BN, (M + BM - 1) / BM);   // (8, 117): N fastest -> A shared in L2
    gemm2x_kernel<<<grid, 256, SMEM_TOTAL>>>(out, M);
}

// round 6
// speedup vs baseline: 5.6928x; 1.0468x over previous
#include <cuda_runtime.h>
#include <cuda_fp16.h>
#include <cstdint>

// out[M,1024] = merged[M,4096] @ W[4096,1024], fp32 via 2-pass fp16 HMMA:
//   out ≈ fp16(A)·Bh + fp16(A)·Bl, where W = Bh + Bl (fp16 2-term split).
// merged row m = concat of 4 gathered rows of image_features (2x2 patch merge).

#define PATCH 14
#define HID   1024
#define KTOT  4096
#define MPAD  15104

#define BM 128
#define BN 128
#define BK 64                      // 64 halves = 128 B row: natural SW128 atom
#define NCHUNK (KTOT / BK)         // 64
#define TILE_B (128 * 128)         // 16384 B (128 rows x 128 B), XOR-swizzled
#define STAGE_B (3 * TILE_B)       // 49152 : Ah | Bh | Bl
#define NSTAGE 2
#define SMEM_TOTAL (NSTAGE * STAGE_B)   // 98304 -> 2 CTAs/SM

// scratch (static device memory — no runtime allocation)
__device__ __align__(128) __half g_Ah[(size_t)MPAD * KTOT];
__device__ __align__(128) __half g_Bh[(size_t)HID * KTOT];
__device__ __align__(128) __half g_Bl[(size_t)HID * KTOT];

// ─── prep: gather + fp32 -> fp16 into merged [M,4096] layout ────────────────
// one block per merged row m; 256 threads: thread t -> ki = t>>6, 16 floats
__global__ void convert_A_kernel(const float* __restrict__ feat,
                                 const int* __restrict__ sizes, int n_images) {
    __shared__ int s_src[4];
    const int m = blockIdx.x;
    const int tid = threadIdx.x;
    if (tid < 4) {
        int toff = 0, moff = 0, src = 0;
        for (int i = 0; i < n_images; i++) {
            const int h = sizes[2 * i] / PATCH, w = sizes[2 * i + 1] / PATCH;
            const int w2 = w >> 1, mr = (h >> 1) * w2;
            if (m < moff + mr) {
                const int r = m - moff;
                const int gr = r / w2, gc = r - gr * w2;
                src = toff + (2 * gr + (tid >> 1)) * w + 2 * gc + (tid & 1);
                break;
            }
            toff += h * w; moff += mr;
        }
        s_src[tid] = src;
    }
    __syncthreads();
    const int ki = tid >> 6;
    const int c  = (tid & 63) * 16;
    const float4* src = (const float4*)(feat + (size_t)s_src[ki] * HID + c);
    const float4 x0 = src[0], x1 = src[1], x2 = src[2], x3 = src[3];
    __half2 h[8];
    h[0] = __floats2half2_rn(x0.x, x0.y); h[1] = __floats2half2_rn(x0.z, x0.w);
    h[2] = __floats2half2_rn(x1.x, x1.y); h[3] = __floats2half2_rn(x1.z, x1.w);
    h[4] = __floats2half2_rn(x2.x, x2.y); h[5] = __floats2half2_rn(x2.z, x2.w);
    h[6] = __floats2half2_rn(x3.x, x3.y); h[7] = __floats2half2_rn(x3.z, x3.w);
    float4* dst = (float4*)(g_Ah + (size_t)m * KTOT + ki * HID + c);
    dst[0] = *(float4*)&h[0];
    dst[1] = *(float4*)&h[4];
}

// ─── prep: transpose W[4096,1024] -> [1024,4096] K-major, fp16 hi/lo ────────
__global__ void convert_W_kernel(const float* __restrict__ Wm) {
    __shared__ float tile[32][33];
    const int k0 = blockIdx.x * 32, n0 = blockIdx.y * 32;
    const int tx = threadIdx.x, ty = threadIdx.y;
    #pragma unroll
    for (int i = 0; i < 4; i++)
        tile[ty + i * 8][tx] = Wm[(size_t)(k0 + ty + i * 8) * HID + n0 + tx];
    __syncthreads();
    #pragma unroll
    for (int i = 0; i < 4; i++) {
        const float x = tile[tx][ty + i * 8];
        const __half h = __float2half_rn(x);
        const __half l = __float2half_rn(x - __half2float(h));
        const size_t o = (size_t)(n0 + ty + i * 8) * KTOT + k0 + tx;
        g_Bh[o] = h;
        g_Bl[o] = l;
    }
}

// ─── PTX helpers ────────────────────────────────────────────────────────────
__device__ __forceinline__ uint32_t smem_u32(const void* p) {
    uint32_t a;
    asm("{ .reg .u64 t; cvta.to.shared.u64 t, %1; cvt.u32.u64 %0, t; }" : "=r"(a) : "l"(p));
    return a;
}
__device__ __forceinline__ void cp16(uint32_t dst, const void* src) {
    asm volatile("cp.async.cg.shared.global [%0], [%1], 16;" :: "r"(dst), "l"(src));
}
__device__ __forceinline__ void ldsm_x4(uint32_t* r, uint32_t addr) {
    asm volatile("ldmatrix.sync.aligned.m8n8.x4.shared.b16 {%0,%1,%2,%3}, [%4];"
        : "=r"(r[0]), "=r"(r[1]), "=r"(r[2]), "=r"(r[3]) : "r"(addr));
}
__device__ __forceinline__ void mma_f16(float* c, const uint32_t* a, const uint32_t* b) {
    asm volatile("mma.sync.aligned.m16n8k16.row.col.f32.f16.f16.f32 "
        "{%0,%1,%2,%3}, {%4,%5,%6,%7}, {%8,%9}, {%0,%1,%2,%3};"
        : "+f"(c[0]), "+f"(c[1]), "+f"(c[2]), "+f"(c[3])
        : "r"(a[0]), "r"(a[1]), "r"(a[2]), "r"(a[3]), "r"(b[0]), "r"(b[1]));
}

// ─── main GEMM: 128x128 CTA, 8 warps (64x32 warp tile), BK=64, 1 bar/iter ───
__global__ __launch_bounds__(256, 2) void gemm2x_kernel(float* __restrict__ out, int M) {
    extern __shared__ __align__(128) char smem[];
    const uint32_t sb = smem_u32(smem);
    const int tid  = threadIdx.x;
    const int lane = tid & 31;
    const int wid  = tid >> 5;
    const int wm   = wid & 1;
    const int wn   = wid >> 1;

    const int m0 = blockIdx.y * BM;
    const int n0 = blockIdx.x * BN;

    // cp.async mapping: tile = 128 rows x 8 x 16B; thread t covers segs t+256j
    int cp_row[4], cp_col[4];
    uint32_t cp_dst[4];
    #pragma unroll
    for (int j = 0; j < 4; j++) {
        const int s = tid + 256 * j;
        cp_row[j] = s >> 3;
        cp_col[j] = s & 7;
        cp_dst[j] = cp_row[j] * 128 + ((cp_col[j] ^ (cp_row[j] & 7)) << 4);
    }
    int gra[4], grb[4];
    #pragma unroll
    for (int j = 0; j < 4; j++) {
        gra[j] = min(m0 + cp_row[j], M - 1);
        grb[j] = n0 + cp_row[j];
    }

    float acc[4][4][4];
    #pragma unroll
    for (int i = 0; i < 4; i++)
        #pragma unroll
        for (int j = 0; j < 4; j++)
            #pragma unroll
            for (int q = 0; q < 4; q++) acc[i][j][q] = 0.0f;

    // ldmatrix lane-constant pieces (swizzle bits constant: row offsets % 8 == 0)
    const int arow = wm * 64 + (lane & 15);
    const int asel = lane >> 4;
    const int aswz = arow & 7;
    const int brow = wn * 32 + ((lane >> 4) & 1) * 8 + (lane & 7);
    const int bsel = (lane >> 3) & 1;
    const int bswz = brow & 7;

    auto cp_chunk = [&](int c, int st) {
        const uint32_t base = sb + st * STAGE_B;
        const int k0 = c * BK;
        #pragma unroll
        for (int j = 0; j < 4; j++) {
            const int ko = k0 + cp_col[j] * 8;
            cp16(base + cp_dst[j],              g_Ah + (size_t)gra[j] * KTOT + ko);
            cp16(base + TILE_B + cp_dst[j],     g_Bh + (size_t)grb[j] * KTOT + ko);
            cp16(base + 2 * TILE_B + cp_dst[j], g_Bl + (size_t)grb[j] * KTOT + ko);
        }
    };

    auto compute_chunk = [&](int st) {
        const uint32_t base = sb + st * STAGE_B;
        #pragma unroll
        for (int kk = 0; kk < 4; kk++) {
            uint32_t a[4][4], bh[2][4], bl[2][4];
            const uint32_t acol = (uint32_t)(((kk * 2 + asel) ^ aswz) << 4);
            const uint32_t bcol = (uint32_t)(((kk * 2 + bsel) ^ bswz) << 4);
            #pragma unroll
            for (int i = 0; i < 4; i++)
                ldsm_x4(a[i], base + (arow + i * 16) * 128 + acol);
            #pragma unroll
            for (int jj = 0; jj < 2; jj++)
                ldsm_x4(bh[jj], base + TILE_B + (brow + jj * 16) * 128 + bcol);
            #pragma unroll
            for (int jj = 0; jj < 2; jj++)
                ldsm_x4(bl[jj], base + 2 * TILE_B + (brow + jj * 16) * 128 + bcol);
            #pragma unroll
            for (int i = 0; i < 4; i++)
                #pragma unroll
                for (int j = 0; j < 4; j++)
                    mma_f16(acc[i][j], a[i], &bh[j >> 1][(j & 1) * 2]);
            #pragma unroll
            for (int i = 0; i < 4; i++)
                #pragma unroll
                for (int j = 0; j < 4; j++)
                    mma_f16(acc[i][j], a[i], &bl[j >> 1][(j & 1) * 2]);
        }
    };

    // 2-stage pipeline, ONE barrier per iteration.
    // Safety: cp(c+1) overwrites stage (c+1)&1 == (c-1)&1, last read by
    // compute(c-1); every warp's compute(c-1) precedes the sync at iter c.
    cp_chunk(0, 0);
    asm volatile("cp.async.commit_group;" ::: "memory");

    #pragma unroll 1
    for (int c = 0; c < NCHUNK; c++) {
        asm volatile("cp.async.wait_group 0;" ::: "memory");   // chunk c resident
        __syncthreads();
        if (c + 1 < NCHUNK) {
            cp_chunk(c + 1, (c + 1) & 1);
            asm volatile("cp.async.commit_group;" ::: "memory");
        }
        compute_chunk(c & 1);
    }

    // epilogue
    const int g = lane >> 2, t = lane & 3;
    #pragma unroll
    for (int i = 0; i < 4; i++) {
        #pragma unroll
        for (int j = 0; j < 4; j++) {
            const int r  = m0 + wm * 64 + i * 16 + g;
            const int cc = n0 + wn * 32 + j * 8 + t * 2;
            if (r < M)
                *(float2*)(out + (size_t)r * HID + cc) =
                    make_float2(acc[i][j][0], acc[i][j][1]);
            if (r + 8 < M)
                *(float2*)(out + (size_t)(r + 8) * HID + cc) =
                    make_float2(acc[i][j][2], acc[i][j][3]);
        }
    }
}

// ─── host ───────────────────────────────────────────────────────────────────
extern "C" void kernel_launch(void* const* d_in, const int* in_sizes, int n_in,
                              void* d_out, int out_size) {
    const float* feat  = (const float*)d_in[0];
    const int*   sizes = (const int*)  d_in[1];
    const float* Wm    = (const float*)d_in[2];
    float* out = (float*)d_out;

    const int n_images = in_sizes[1] / 2;
    const int M        = out_size / HID;

    convert_A_kernel<<<M, 256>>>(feat, sizes, n_images);
    convert_W_kernel<<<dim3(KTOT / 32, HID / 32), dim3(32, 8)>>>(Wm);

    static bool attr_set = false;
    if (!attr_set) {
        cudaFuncSetAttribute(gemm2x_kernel,
                             cudaFuncAttributeMaxDynamicSharedMemorySize, SMEM_TOTAL);
        attr_set = true;
    }
    dim3 grid(HID / BN, (M + BM - 1) / BM);   // (8, 117): N fastest -> A shared in L2
    gemm2x_kernel<<<grid, 256, SMEM_TOTAL>>>(out, M);
}

// round 7
// speedup vs baseline: 9.7358x; 1.7102x over previous
#include <cuda_runtime.h>
#include <cuda_fp16.h>
#include <cstdint>

// out[M,1024] = merged[M,4096] @ W[4096,1024], fp32 via SINGLE-pass fp16 HMMA:
//   out ≈ fp16(A) · fp16(W).  Measured error budget: A-quant alone gave
//   2.078e-4; adding B-quant ≈ sqrt(2)x ≈ 3e-4, well under the 1e-3 bar.
// merged row m = concat of 4 gathered rows of image_features (2x2 patch merge).

#define PATCH 14
#define HID   1024
#define KTOT  4096
#define MPAD  15104

#define BM 128
#define BN 128
#define BK 64                      // 64 halves = 128 B row: natural SW128 atom
#define NCHUNK (KTOT / BK)         // 64
#define TILE_B (128 * 128)         // 16384 B (128 rows x 128 B), XOR-swizzled
#define STAGE_B (2 * TILE_B)       // 32768 : Ah | Bh
#define NSTAGE 3
#define SMEM_TOTAL (NSTAGE * STAGE_B)   // 98304 -> 2 CTAs/SM

// scratch (static device memory — no runtime allocation)
__device__ __align__(128) __half g_Ah[(size_t)MPAD * KTOT];
__device__ __align__(128) __half g_Bh[(size_t)HID * KTOT];

// ─── prep: gather + fp32 -> fp16 into merged [M,4096] layout ────────────────
__global__ void convert_A_kernel(const float* __restrict__ feat,
                                 const int* __restrict__ sizes, int n_images) {
    __shared__ int s_src[4];
    const int m = blockIdx.x;
    const int tid = threadIdx.x;
    if (tid < 4) {
        int toff = 0, moff = 0, src = 0;
        for (int i = 0; i < n_images; i++) {
            const int h = sizes[2 * i] / PATCH, w = sizes[2 * i + 1] / PATCH;
            const int w2 = w >> 1, mr = (h >> 1) * w2;
            if (m < moff + mr) {
                const int r = m - moff;
                const int gr = r / w2, gc = r - gr * w2;
                src = toff + (2 * gr + (tid >> 1)) * w + 2 * gc + (tid & 1);
                break;
            }
            toff += h * w; moff += mr;
        }
        s_src[tid] = src;
    }
    __syncthreads();
    const int ki = tid >> 6;
    const int c  = (tid & 63) * 16;
    const float4* src = (const float4*)(feat + (size_t)s_src[ki] * HID + c);
    const float4 x0 = src[0], x1 = src[1], x2 = src[2], x3 = src[3];
    __half2 h[8];
    h[0] = __floats2half2_rn(x0.x, x0.y); h[1] = __floats2half2_rn(x0.z, x0.w);
    h[2] = __floats2half2_rn(x1.x, x1.y); h[3] = __floats2half2_rn(x1.z, x1.w);
    h[4] = __floats2half2_rn(x2.x, x2.y); h[5] = __floats2half2_rn(x2.z, x2.w);
    h[6] = __floats2half2_rn(x3.x, x3.y); h[7] = __floats2half2_rn(x3.z, x3.w);
    float4* dst = (float4*)(g_Ah + (size_t)m * KTOT + ki * HID + c);
    dst[0] = *(float4*)&h[0];
    dst[1] = *(float4*)&h[4];
}

// ─── prep: transpose W[4096,1024] -> [1024,4096] K-major fp16 ───────────────
__global__ void convert_W_kernel(const float* __restrict__ Wm) {
    __shared__ float tile[32][33];
    const int k0 = blockIdx.x * 32, n0 = blockIdx.y * 32;
    const int tx = threadIdx.x, ty = threadIdx.y;
    #pragma unroll
    for (int i = 0; i < 4; i++)
        tile[ty + i * 8][tx] = Wm[(size_t)(k0 + ty + i * 8) * HID + n0 + tx];
    __syncthreads();
    #pragma unroll
    for (int i = 0; i < 4; i++) {
        const float x = tile[tx][ty + i * 8];
        g_Bh[(size_t)(n0 + ty + i * 8) * KTOT + k0 + tx] = __float2half_rn(x);
    }
}

// ─── PTX helpers ────────────────────────────────────────────────────────────
__device__ __forceinline__ uint32_t smem_u32(const void* p) {
    uint32_t a;
    asm("{ .reg .u64 t; cvta.to.shared.u64 t, %1; cvt.u32.u64 %0, t; }" : "=r"(a) : "l"(p));
    return a;
}
__device__ __forceinline__ void cp16(uint32_t dst, const void* src) {
    asm volatile("cp.async.cg.shared.global [%0], [%1], 16;" :: "r"(dst), "l"(src));
}
__device__ __forceinline__ void ldsm_x4(uint32_t* r, uint32_t addr) {
    asm volatile("ldmatrix.sync.aligned.m8n8.x4.shared.b16 {%0,%1,%2,%3}, [%4];"
        : "=r"(r[0]), "=r"(r[1]), "=r"(r[2]), "=r"(r[3]) : "r"(addr));
}
__device__ __forceinline__ void mma_f16(float* c, const uint32_t* a, const uint32_t* b) {
    asm volatile("mma.sync.aligned.m16n8k16.row.col.f32.f16.f16.f32 "
        "{%0,%1,%2,%3}, {%4,%5,%6,%7}, {%8,%9}, {%0,%1,%2,%3};"
        : "+f"(c[0]), "+f"(c[1]), "+f"(c[2]), "+f"(c[3])
        : "r"(a[0]), "r"(a[1]), "r"(a[2]), "r"(a[3]), "r"(b[0]), "r"(b[1]));
}

// ─── main GEMM: 128x128 CTA, 8 warps (64x32), BK=64, 3-stage, 1 bar/iter ────
__global__ __launch_bounds__(256, 2) void gemm1x_kernel(float* __restrict__ out, int M) {
    extern __shared__ __align__(128) char smem[];
    const uint32_t sb = smem_u32(smem);
    const int tid  = threadIdx.x;
    const int lane = tid & 31;
    const int wid  = tid >> 5;
    const int wm   = wid & 1;
    const int wn   = wid >> 1;

    const int m0 = blockIdx.y * BM;
    const int n0 = blockIdx.x * BN;

    // cp.async mapping: tile = 128 rows x 8 x 16B; thread t covers segs t+256j
    int cp_row[4], cp_col[4];
    uint32_t cp_dst[4];
    #pragma unroll
    for (int j = 0; j < 4; j++) {
        const int s = tid + 256 * j;
        cp_row[j] = s >> 3;
        cp_col[j] = s & 7;
        cp_dst[j] = cp_row[j] * 128 + ((cp_col[j] ^ (cp_row[j] & 7)) << 4);
    }
    int gra[4], grb[4];
    #pragma unroll
    for (int j = 0; j < 4; j++) {
        gra[j] = min(m0 + cp_row[j], M - 1);
        grb[j] = n0 + cp_row[j];
    }

    float acc[4][4][4];
    #pragma unroll
    for (int i = 0; i < 4; i++)
        #pragma unroll
        for (int j = 0; j < 4; j++)
            #pragma unroll
            for (int q = 0; q < 4; q++) acc[i][j][q] = 0.0f;

    // ldmatrix lane-constant pieces (swizzle bits constant: row offsets % 8 == 0)
    const int arow = wm * 64 + (lane & 15);
    const int asel = lane >> 4;
    const int aswz = arow & 7;
    const int brow = wn * 32 + ((lane >> 4) & 1) * 8 + (lane & 7);
    const int bsel = (lane >> 3) & 1;
    const int bswz = brow & 7;

    auto cp_chunk = [&](int c, int st) {
        const uint32_t base = sb + st * STAGE_B;
        const int k0 = c * BK;
        #pragma unroll
        for (int j = 0; j < 4; j++) {
            const int ko = k0 + cp_col[j] * 8;
            cp16(base + cp_dst[j],          g_Ah + (size_t)gra[j] * KTOT + ko);
            cp16(base + TILE_B + cp_dst[j], g_Bh + (size_t)grb[j] * KTOT + ko);
        }
    };

    auto compute_chunk = [&](int st) {
        const uint32_t base = sb + st * STAGE_B;
        #pragma unroll
        for (int kk = 0; kk < 4; kk++) {
            uint32_t a[4][4], bh[2][4];
            const uint32_t acol = (uint32_t)(((kk * 2 + asel) ^ aswz) << 4);
            const uint32_t bcol = (uint32_t)(((kk * 2 + bsel) ^ bswz) << 4);
            #pragma unroll
            for (int i = 0; i < 4; i++)
                ldsm_x4(a[i], base + (arow + i * 16) * 128 + acol);
            #pragma unroll
            for (int jj = 0; jj < 2; jj++)
                ldsm_x4(bh[jj], base + TILE_B + (brow + jj * 16) * 128 + bcol);
            #pragma unroll
            for (int i = 0; i < 4; i++)
                #pragma unroll
                for (int j = 0; j < 4; j++)
                    mma_f16(acc[i][j], a[i], &bh[j >> 1][(j & 1) * 2]);
        }
    };

    // 3-stage pipeline, one barrier per iteration, wait_group 1 slack.
    // Group G(c+2) is committed at iter c (empty when no cp issued), so
    // "wait_group 1" at iter c guarantees exactly cp(c) resident while
    // cp(c+1) may still be in flight. cp(c+2) overwrites stage (c-1)%3,
    // last read by compute(c-1) which all warps finished before this
    // iteration's barrier.
    cp_chunk(0, 0);
    asm volatile("cp.async.commit_group;" ::: "memory");
    cp_chunk(1, 1);
    asm volatile("cp.async.commit_group;" ::: "memory");

    int st_c = 0, st_p = 2;
    #pragma unroll 1
    for (int c = 0; c < NCHUNK; c++) {
        asm volatile("cp.async.wait_group 1;" ::: "memory");   // cp(c) resident
        __syncthreads();
        if (c + 2 < NCHUNK) cp_chunk(c + 2, st_p);
        asm volatile("cp.async.commit_group;" ::: "memory");   // may be empty
        compute_chunk(st_c);
        if (++st_c == NSTAGE) st_c = 0;
        if (++st_p == NSTAGE) st_p = 0;
    }

    // epilogue
    const int g = lane >> 2, t = lane & 3;
    #pragma unroll
    for (int i = 0; i < 4; i++) {
        #pragma unroll
        for (int j = 0; j < 4; j++) {
            const int r  = m0 + wm * 64 + i * 16 + g;
            const int cc = n0 + wn * 32 + j * 8 + t * 2;
            if (r < M)
                *(float2*)(out + (size_t)r * HID + cc) =
                    make_float2(acc[i][j][0], acc[i][j][1]);
            if (r + 8 < M)
                *(float2*)(out + (size_t)(r + 8) * HID + cc) =
                    make_float2(acc[i][j][2], acc[i][j][3]);
        }
    }
}

// ─── host ───────────────────────────────────────────────────────────────────
extern "C" void kernel_launch(void* const* d_in, const int* in_sizes, int n_in,
                              void* d_out, int out_size) {
    const float* feat  = (const float*)d_in[0];
    const int*   sizes = (const int*)  d_in[1];
    const float* Wm    = (const float*)d_in[2];
    float* out = (float*)d_out;

    const int n_images = in_sizes[1] / 2;
    const int M        = out_size / HID;

    convert_A_kernel<<<M, 256>>>(feat, sizes, n_images);
    convert_W_kernel<<<dim3(KTOT / 32, HID / 32), dim3(32, 8)>>>(Wm);

    static bool attr_set = false;
    if (!attr_set) {
        cudaFuncSetAttribute(gemm1x_kernel,
                             cudaFuncAttributeMaxDynamicSharedMemorySize, SMEM_TOTAL);
        attr_set = true;
    }
    dim3 grid(HID / BN, (M + BM - 1) / BM);   // (8, 117): N fastest -> A shared in L2
    gemm1x_kernel<<<grid, 256, SMEM_TOTAL>>>(out, M);
}